// round 9
// baseline (speedup 1.0000x reference)
#include <cuda_runtime.h>
#include <cstdint>

#define WINDOW 40
#define EE 8
#define NSTOCK 8000
#define TDIM 64
#define FDIM 64
#define INCH 144
#define LOUT 36

__device__ float g_rank[WINDOW * EE * NSTOCK];      // [col][n]
__device__ float g_rank_t[NSTOCK * WINDOW * EE];    // [n][col]

// Φ^{-1}(k/32), k=1..31 — breakpoints for N(0,1) equidistribution
__constant__ float c_z[31] = {
    -1.862732f, -1.534121f, -1.318011f, -1.150349f, -1.009990f,
    -0.887147f, -0.776422f, -0.674490f, -0.579132f, -0.488776f,
    -0.402250f, -0.318639f, -0.237202f, -0.157311f, -0.078412f,
     0.000000f,  0.078412f,  0.157311f,  0.237202f,  0.318639f,
     0.402250f,  0.488776f,  0.579132f,  0.674490f,  0.776422f,
     0.887147f,  1.009990f,  1.150349f,  1.318011f,  1.534121f,
     1.862732f };

// ---------------------------------------------------------------------------
// Kernel A: exact descending rank. Direct 8192-bin CDF-table binning
// (monotone integer piecewise-linear map), one histogram, u64 tie-break pack.
// smem: keyb 33w | scale 32w | pad | h2p 4100w | pack 8000 u64  = 80672 B
// ---------------------------------------------------------------------------
#define RT 512
#define KEYB_OFF 0
#define SCALE_OFF 33
#define H2P_OFF 68                    // word offset, 16B aligned
#define H2W 4100
#define PACK_OFF (H2P_OFF + H2W)      // 4168 words -> byte 16672, 8B aligned
#define SMEM_R (PACK_OFF * 4 + NSTOCK * 8)

__device__ __forceinline__ unsigned int okey(float f) {
    unsigned int u = __float_as_uint(f);
    return (u & 0x80000000u) ? ~u : (u | 0x80000000u);
}

__global__ void __launch_bounds__(RT, 2) rank_kernel(const float* __restrict__ x) {
    extern __shared__ unsigned char smem_raw[];
    unsigned int* keyb  = (unsigned int*)smem_raw + KEYB_OFF;   // 33 breakpoint keys
    unsigned int* scale = (unsigned int*)smem_raw + SCALE_OFF;  // 32 per-segment scales
    unsigned int* h2p   = (unsigned int*)smem_raw + H2P_OFF;    // 8192 bins packed u16 (+sentinel)
    unsigned long long* pack = (unsigned long long*)((unsigned int*)smem_raw + PACK_OFF);

    __shared__ unsigned int wsum[16];

    const int col = blockIdx.x;
    const int tw  = col >> 3;
    const int e   = col & 7;
    const int tid = threadIdx.x;
    const unsigned int lane = tid & 31u;
    const unsigned int wid  = tid >> 5;

    // setup: breakpoints, scales, zero histogram
    if (tid < 33) {
        unsigned int k;
        if (tid == 0)       k = 0u;
        else if (tid == 32) k = 0xFFFFFFFFu;
        else                k = okey(c_z[tid - 1]);
        keyb[tid] = k;
    }
    {
        uint4 z4 = make_uint4(0u, 0u, 0u, 0u);
        uint4* h2v = (uint4*)h2p;
#pragma unroll
        for (int i = 0; i < 2; i++) h2v[tid + (i << 9)] = z4;   // 4096 words
        if (tid == 0) { h2p[4096] = 0u; h2p[4097] = 0u; h2p[4098] = 0u; h2p[4099] = 0u; }
    }
    __syncthreads();
    if (tid < 32) {
        unsigned long long range = (unsigned long long)(keyb[tid + 1] - keyb[tid]);
        if (range == 0ull) range = 1ull;
        unsigned long long sc = (256ull << 32) / range;
        scale[tid] = (sc > 0xFFFFFFFFull) ? 0xFFFFFFFFu : (unsigned int)sc;
    }
    __syncthreads();

    const float* basep = x + (24 + tw) * FDIM + e;

    // P1: load key, CDF-bin, histogram (atomic old = within-bin index)
    unsigned int rk[16], lv[16];
#pragma unroll
    for (int i = 0; i < 16; i++) {
        int n = tid + (i << 9);
        if (n < NSTOCK) {
            unsigned int u = okey(__ldg(basep + (size_t)n * (TDIM * FDIM)));
            rk[i] = u;
            unsigned int s = (u >= keyb[16]) ? 16u : 0u;
            s |= (u >= keyb[s | 8u]) ? 8u : 0u;
            s |= (u >= keyb[s | 4u]) ? 4u : 0u;
            s |= (u >= keyb[s | 2u]) ? 2u : 0u;
            s |= (u >= keyb[s | 1u]) ? 1u : 0u;
            unsigned int sub = (unsigned int)(((unsigned long long)(u - keyb[s]) *
                                              (unsigned long long)scale[s]) >> 32);
            sub = (sub > 255u) ? 255u : sub;
            unsigned int l2 = (s << 8) | sub;
            unsigned int old = atomicAdd(&h2p[l2 >> 1], (l2 & 1u) ? 65536u : 1u);
            unsigned int idx = (old >> ((l2 & 1u) * 16u)) & 0xFFFFu;
            lv[i] = (l2 << 16) | idx;
        }
    }
    __syncthreads();

    // exclusive prefix over 8192 bins; word w -> start(2w) | start(2w+1)<<16
    {
        uint4* h2v = (uint4*)h2p;
        uint4 a[2];
        unsigned int s = 0;
#pragma unroll
        for (int j = 0; j < 2; j++) {
            a[j] = h2v[tid * 2 + j];
            s += (a[j].x & 0xFFFFu) + (a[j].x >> 16) + (a[j].y & 0xFFFFu) + (a[j].y >> 16)
               + (a[j].z & 0xFFFFu) + (a[j].z >> 16) + (a[j].w & 0xFFFFu) + (a[j].w >> 16);
        }
        unsigned int v = s;
#pragma unroll
        for (int o = 1; o < 32; o <<= 1) {
            unsigned int t = __shfl_up_sync(0xFFFFFFFFu, v, o);
            if (lane >= (unsigned)o) v += t;
        }
        if (lane == 31u) wsum[wid] = v;
        __syncthreads();
        if (wid == 0) {
            unsigned int orig = (lane < 16u) ? wsum[lane] : 0u;
            unsigned int w = orig;
#pragma unroll
            for (int o = 1; o < 32; o <<= 1) {
                unsigned int t = __shfl_up_sync(0xFFFFFFFFu, w, o);
                if (lane >= (unsigned)o) w += t;
            }
            if (lane < 16u) wsum[lane] = w - orig;
        }
        __syncthreads();
        unsigned int run = wsum[wid] + (v - s);
#pragma unroll
        for (int j = 0; j < 2; j++) {
            unsigned int* p = &a[j].x;
#pragma unroll
            for (int k = 0; k < 4; k++) {
                unsigned int w = p[k];
                unsigned int lo = w & 0xFFFFu, hi = w >> 16;
                p[k] = run | ((run + lo) << 16);
                run += lo + hi;
            }
            h2v[tid * 2 + j] = a[j];
        }
        if (tid == 0) h2p[4096] = (unsigned int)NSTOCK;   // sentinel start(8192)
    }
    __syncthreads();

    // P3: scatter u64 tie-break keys (no atomics): pos = start(l2) + idx
#pragma unroll
    for (int i = 0; i < 16; i++) {
        int n = tid + (i << 9);
        if (n < NSTOCK) {
            unsigned int l2 = lv[i] >> 16;
            unsigned int idx = lv[i] & 0xFFFFu;
            unsigned int w = h2p[l2 >> 1];
            unsigned int start = (w >> ((l2 & 1u) * 16u)) & 0xFFFFu;
            pack[start + idx] = ((unsigned long long)rk[i] << 13) | (8191u - (unsigned)n);
        }
    }
    __syncthreads();

    // P4: rank = above-segment + in-segment strictly-greater; coalesced store
    float* dst = g_rank + (size_t)col * NSTOCK;
#pragma unroll
    for (int i = 0; i < 16; i++) {
        int n = tid + (i << 9);
        if (n < NSTOCK) {
            unsigned int l2 = lv[i] >> 16;
            unsigned int ws = h2p[l2 >> 1];
            unsigned int start = (ws >> ((l2 & 1u) * 16u)) & 0xFFFFu;
            unsigned int l2e = l2 + 1u;
            unsigned int we = h2p[l2e >> 1];
            unsigned int end = (we >> ((l2e & 1u) * 16u)) & 0xFFFFu;
            unsigned long long K = ((unsigned long long)rk[i] << 13) | (8191u - (unsigned)n);
            unsigned int g = (unsigned int)NSTOCK - end;
            for (unsigned int q = start; q < end; q++)
                g += (pack[q] > K) ? 1u : 0u;
            dst[n] = (float)g * (1.0f / (float)NSTOCK);
        }
    }
}

// ---------------------------------------------------------------------------
// Transpose [col][n] -> [n][col]
// ---------------------------------------------------------------------------
__global__ void transpose_kernel() {
    __shared__ float tile[32][33];
    const int c0 = blockIdx.x * 32;
    const int n0 = blockIdx.y * 32;
    const int tx = threadIdx.x, ty = threadIdx.y;
    tile[ty][tx] = g_rank[(size_t)(c0 + ty) * NSTOCK + n0 + tx];
    __syncthreads();
    g_rank_t[(size_t)(n0 + ty) * (WINDOW * EE) + c0 + tx] = tile[tx][ty];
}

// ---------------------------------------------------------------------------
// Kernel B: fused stats + conv (out-channel 127) + linear.
// Reduction: 2-level butterfly -> 8 partials/warp -> smem -> 36-thread finish.
// ---------------------------------------------------------------------------
#define SID_STRIDE 328

__global__ void __launch_bounds__(320) main_kernel(
    const float* __restrict__ x,
    const float* __restrict__ conv_w,
    const float* __restrict__ conv_b,
    const float* __restrict__ lin_w,
    const float* __restrict__ lin_b,
    float* __restrict__ out)
{
    __shared__ __align__(16) float xe[59][8];
    __shared__ __align__(16) float stats[8 * SID_STRIDE];
    __shared__ __align__(16) float rank_row[WINDOW * EE];
    __shared__ float red[80][18];            // [warp*8 + group][j]
    __shared__ float fin[LOUT];

    const int n = blockIdx.x;
    const int tid = threadIdx.x;
    const float* xn = x + (size_t)n * (TDIM * FDIM);

    for (int i = tid; i < 59 * 8; i += 320) {
        int tt = i >> 3, ee = i & 7;
        xe[tt][ee] = __ldg(xn + (5 + tt) * FDIM + ee);
    }
    if (tid < (WINDOW * EE) / 4) {
        const float4* rsrc = (const float4*)(g_rank_t + (size_t)n * (WINDOW * EE));
        ((float4*)rank_row)[tid] = rsrc[tid];
    }
    __syncthreads();

    // stats: one (tw, ee) task per thread, single pass
    {
        int tw = tid >> 3, ee = tid & 7;
        int te = 19 + tw;

        float s20 = 0.f, q20 = 0.f, mx20 = -1e30f, mn20 = 1e30f;
        float s5 = 0.f, q5 = 0.f, mx5 = -1e30f, mn5 = 1e30f;
#pragma unroll
        for (int j = 0; j < 20; j++) {
            float v = xe[te - 19 + j][ee];
            s20 += v; q20 = fmaf(v, v, q20);
            mx20 = fmaxf(mx20, v); mn20 = fminf(mn20, v);
            if (j >= 15) {
                s5 += v; q5 = fmaf(v, v, q5);
                mx5 = fmaxf(mx5, v); mn5 = fminf(mn5, v);
            }
        }
        float m20 = s20 * 0.05f;
        float m5  = s5 * 0.2f;
        float sd20 = sqrtf(fmaxf(fmaf(-s20, m20, q20), 0.f) * (1.0f / 19.0f));
        float sd5  = sqrtf(fmaxf(fmaf(-s5, m5, q5), 0.f) * 0.25f);

        float* st = stats + tw * 8 + ee;
        st[0 * SID_STRIDE] = m5;   st[1 * SID_STRIDE] = sd5;
        st[2 * SID_STRIDE] = mx5;  st[3 * SID_STRIDE] = mn5;
        st[4 * SID_STRIDE] = m20;  st[5 * SID_STRIDE] = sd20;
        st[6 * SID_STRIDE] = mx20; st[7 * SID_STRIDE] = mn20;
    }
    __syncthreads();

    // conv: two threads per channel, each covering 18 of 36 outputs
    float acc[18];
#pragma unroll
    for (int j = 0; j < 18; j++) acc[j] = 0.f;

    const int hh = (tid >= 160) ? 1 : 0;
    const int c  = tid - hh * 160;
    const int l0 = hh * 18;

    if (c < INCH) {
        const float* wp = conv_w + 127 * (INCH * 5) + c * 5;
        float w0 = __ldg(wp + 0), w1 = __ldg(wp + 1), w2 = __ldg(wp + 2),
              w3 = __ldg(wp + 3), w4 = __ldg(wp + 4);

        if (c < FDIM) {
            const float* src = xn + (24 + l0) * FDIM + c;
#pragma unroll
            for (int tt = 0; tt < 22; tt++) {
                float v = __ldg(src + tt * FDIM);
#pragma unroll
                for (int k = 0; k < 5; k++) {
                    int j = tt - k;
                    if (j >= 0 && j < 18) {
                        float wk = (k == 0) ? w0 : (k == 1) ? w1 : (k == 2) ? w2 : (k == 3) ? w3 : w4;
                        acc[j] += v * wk;
                    }
                }
            }
        } else {
            int cc = c - FDIM;
            int grp = (cc >= 40) ? 1 : 0;
            int r = cc - grp * 40;
            int se = r >> 3;
            int ee = r & 7;
            const float* s_src;
            if (se == 2) {
                s_src = rank_row + ee;
            } else {
                int statid = (se < 2 ? se : se - 1) + grp * 4;
                s_src = stats + statid * SID_STRIDE + ee;
            }
            s_src += l0 * 8;
#pragma unroll
            for (int tt = 0; tt < 22; tt++) {
                float v = s_src[tt * 8];
#pragma unroll
                for (int k = 0; k < 5; k++) {
                    int j = tt - k;
                    if (j >= 0 && j < 18) {
                        float wk = (k == 0) ? w0 : (k == 1) ? w1 : (k == 2) ? w2 : (k == 3) ? w3 : w4;
                        acc[j] += v * wk;
                    }
                }
            }
        }
    }

    // 2-level butterfly: lane holds sum of its group-of-4 {l, l^8, l^16, l^24}
#pragma unroll
    for (int j = 0; j < 18; j++) {
        float a = acc[j];
        a += __shfl_xor_sync(0xFFFFFFFFu, a, 16);
        a += __shfl_xor_sync(0xFFFFFFFFu, a, 8);
        acc[j] = a;
    }
    {
        const int w = tid >> 5;
        if ((tid & 31) < 8) {
#pragma unroll
            for (int j = 0; j < 18; j++) red[w * 8 + (tid & 7)][j] = acc[j];
        }
    }
    __syncthreads();

    if (tid < LOUT) {
        int h2 = (tid >= 18) ? 1 : 0;
        int j = tid - h2 * 18;
        const float* rp = &red[h2 * 40][j];
        float s = __ldg(conv_b + 127);
#pragma unroll
        for (int i = 0; i < 40; i++) s += rp[i * 18];
        float hv = (s >= 0.f) ? s : 0.01f * s;
        fin[tid] = hv * __ldg(lin_w + tid);
    }
    __syncthreads();

    if (tid == 0) {
        float s = __ldg(lin_b);
        for (int l = 0; l < LOUT; l++) s += fin[l];
        out[n] = s;
    }
}

// ---------------------------------------------------------------------------
extern "C" void kernel_launch(void* const* d_in, const int* in_sizes, int n_in,
                              void* d_out, int out_size) {
    const float* x      = (const float*)d_in[0];
    const float* conv_w = (const float*)d_in[1];
    const float* conv_b = (const float*)d_in[2];
    const float* lin_w  = (const float*)d_in[3];
    const float* lin_b  = (const float*)d_in[4];
    float* out = (float*)d_out;

    cudaFuncSetAttribute(rank_kernel, cudaFuncAttributeMaxDynamicSharedMemorySize, SMEM_R);

    rank_kernel<<<WINDOW * EE, RT, SMEM_R>>>(x);
    transpose_kernel<<<dim3((WINDOW * EE) / 32, NSTOCK / 32), dim3(32, 32)>>>();
    main_kernel<<<NSTOCK, 320>>>(x, conv_w, conv_b, lin_w, lin_b, out);
}

// round 10
// speedup vs baseline: 2.1327x; 2.1327x over previous
#include <cuda_runtime.h>
#include <cstdint>

#define WINDOW 40
#define EE 8
#define NSTOCK 8000
#define TDIM 64
#define FDIM 64
#define INCH 144
#define LOUT 36

__device__ float g_rank[WINDOW * EE * NSTOCK];      // [col][n]
__device__ float g_rank_t[NSTOCK * WINDOW * EE];    // [n][col]

// ---------------------------------------------------------------------------
// Kernel A: exact descending rank. Direct monotone VALUE-space binning:
// l2 = clamp(floor((v+4)*1024), 0, 8191). One histogram round (atomic old =
// within-bin index), one prefix, atomic-free scatter, exact u64 in-bin scan.
// smem: h2p 4100 w | pack 8000 u64 = 80400 B -> 2 CTAs/SM.
// ---------------------------------------------------------------------------
#define RT 512
#define H2W 4100
#define SMEM_R (H2W * 4 + NSTOCK * 8)

__device__ __forceinline__ unsigned int okey(float f) {
    unsigned int u = __float_as_uint(f);
    return (u & 0x80000000u) ? ~u : (u | 0x80000000u);
}

__global__ void __launch_bounds__(RT, 2) rank_kernel(const float* __restrict__ x) {
    extern __shared__ unsigned char smem_raw[];
    unsigned int* h2p = (unsigned int*)smem_raw;                       // 8192 bins packed u16 + sentinel
    unsigned long long* pack = (unsigned long long*)(smem_raw + H2W * 4);

    __shared__ unsigned int wsum[16];

    const int col = blockIdx.x;
    const int tw  = col >> 3;
    const int e   = col & 7;
    const int tid = threadIdx.x;
    const unsigned int lane = tid & 31u;
    const unsigned int wid  = tid >> 5;

    // zero histogram
    {
        uint4 z4 = make_uint4(0u, 0u, 0u, 0u);
        uint4* h2v = (uint4*)h2p;
#pragma unroll
        for (int i = 0; i < 2; i++) h2v[tid + (i << 9)] = z4;          // 4096 words
        if (tid == 0) { h2p[4096] = 0u; h2p[4097] = 0u; h2p[4098] = 0u; h2p[4099] = 0u; }
    }
    __syncthreads();

    const float* basep = x + (24 + tw) * FDIM + e;

    // P1: load value, value-space bin, histogram (atomic old = within-bin index)
    unsigned int rk[16], lv[16];
#pragma unroll
    for (int i = 0; i < 16; i++) {
        int n = tid + (i << 9);
        if (n < NSTOCK) {
            float v = __ldg(basep + (size_t)n * (TDIM * FDIM));
            rk[i] = okey(v);
            int b = __float2int_rd(fmaf(v, 1024.0f, 4096.0f));
            b = (b < 0) ? 0 : (b > 8191 ? 8191 : b);
            unsigned int l2 = (unsigned int)b;
            unsigned int old = atomicAdd(&h2p[l2 >> 1], (l2 & 1u) ? 65536u : 1u);
            unsigned int idx = (old >> ((l2 & 1u) * 16u)) & 0xFFFFu;
            lv[i] = (l2 << 16) | idx;
        }
    }
    __syncthreads();

    // exclusive prefix over 8192 bins; word w -> start(2w) | start(2w+1)<<16
    {
        uint4* h2v = (uint4*)h2p;
        uint4 a[2];
        unsigned int s = 0;
#pragma unroll
        for (int j = 0; j < 2; j++) {
            a[j] = h2v[tid * 2 + j];
            s += (a[j].x & 0xFFFFu) + (a[j].x >> 16) + (a[j].y & 0xFFFFu) + (a[j].y >> 16)
               + (a[j].z & 0xFFFFu) + (a[j].z >> 16) + (a[j].w & 0xFFFFu) + (a[j].w >> 16);
        }
        unsigned int v = s;
#pragma unroll
        for (int o = 1; o < 32; o <<= 1) {
            unsigned int t = __shfl_up_sync(0xFFFFFFFFu, v, o);
            if (lane >= (unsigned)o) v += t;
        }
        if (lane == 31u) wsum[wid] = v;
        __syncthreads();
        if (wid == 0) {
            unsigned int orig = (lane < 16u) ? wsum[lane] : 0u;
            unsigned int w = orig;
#pragma unroll
            for (int o = 1; o < 32; o <<= 1) {
                unsigned int t = __shfl_up_sync(0xFFFFFFFFu, w, o);
                if (lane >= (unsigned)o) w += t;
            }
            if (lane < 16u) wsum[lane] = w - orig;
        }
        __syncthreads();
        unsigned int run = wsum[wid] + (v - s);
#pragma unroll
        for (int j = 0; j < 2; j++) {
            unsigned int* p = &a[j].x;
#pragma unroll
            for (int k = 0; k < 4; k++) {
                unsigned int w = p[k];
                unsigned int lo = w & 0xFFFFu, hi = w >> 16;
                p[k] = run | ((run + lo) << 16);
                run += lo + hi;
            }
            h2v[tid * 2 + j] = a[j];
        }
        if (tid == 0) h2p[4096] = (unsigned int)NSTOCK;                // sentinel start(8192)
    }
    __syncthreads();

    // P3: scatter u64 tie-break keys (no atomics): pos = start(l2) + idx
#pragma unroll
    for (int i = 0; i < 16; i++) {
        int n = tid + (i << 9);
        if (n < NSTOCK) {
            unsigned int l2 = lv[i] >> 16;
            unsigned int idx = lv[i] & 0xFFFFu;
            unsigned int w = h2p[l2 >> 1];
            unsigned int start = (w >> ((l2 & 1u) * 16u)) & 0xFFFFu;
            pack[start + idx] = ((unsigned long long)rk[i] << 13) | (8191u - (unsigned)n);
        }
    }
    __syncthreads();

    // P4: rank = above-segment + in-segment strictly-greater; coalesced store
    float* dst = g_rank + (size_t)col * NSTOCK;
#pragma unroll
    for (int i = 0; i < 16; i++) {
        int n = tid + (i << 9);
        if (n < NSTOCK) {
            unsigned int l2 = lv[i] >> 16;
            unsigned int ws = h2p[l2 >> 1];
            unsigned int start = (ws >> ((l2 & 1u) * 16u)) & 0xFFFFu;
            unsigned int l2e = l2 + 1u;
            unsigned int we = h2p[l2e >> 1];
            unsigned int end = (we >> ((l2e & 1u) * 16u)) & 0xFFFFu;
            unsigned long long K = ((unsigned long long)rk[i] << 13) | (8191u - (unsigned)n);
            unsigned int g = (unsigned int)NSTOCK - end;
            for (unsigned int q = start; q < end; q++)
                g += (pack[q] > K) ? 1u : 0u;
            dst[n] = (float)g * (1.0f / (float)NSTOCK);
        }
    }
}

// ---------------------------------------------------------------------------
// Transpose [col][n] -> [n][col]
// ---------------------------------------------------------------------------
__global__ void transpose_kernel() {
    __shared__ float tile[32][33];
    const int c0 = blockIdx.x * 32;
    const int n0 = blockIdx.y * 32;
    const int tx = threadIdx.x, ty = threadIdx.y;
    tile[ty][tx] = g_rank[(size_t)(c0 + ty) * NSTOCK + n0 + tx];
    __syncthreads();
    g_rank_t[(size_t)(n0 + ty) * (WINDOW * EE) + c0 + tx] = tile[tx][ty];
}

// ---------------------------------------------------------------------------
// Kernel B: fused stats + conv (out-channel 127) + linear.
// ---------------------------------------------------------------------------
#define SID_STRIDE 328

__global__ void __launch_bounds__(320) main_kernel(
    const float* __restrict__ x,
    const float* __restrict__ conv_w,
    const float* __restrict__ conv_b,
    const float* __restrict__ lin_w,
    const float* __restrict__ lin_b,
    float* __restrict__ out)
{
    __shared__ __align__(16) float xe[59][8];
    __shared__ __align__(16) float stats[8 * SID_STRIDE];
    __shared__ __align__(16) float rank_row[WINDOW * EE];
    __shared__ float red[80][18];
    __shared__ float fin[LOUT];

    const int n = blockIdx.x;
    const int tid = threadIdx.x;
    const float* xn = x + (size_t)n * (TDIM * FDIM);

    for (int i = tid; i < 59 * 8; i += 320) {
        int tt = i >> 3, ee = i & 7;
        xe[tt][ee] = __ldg(xn + (5 + tt) * FDIM + ee);
    }
    if (tid < (WINDOW * EE) / 4) {
        const float4* rsrc = (const float4*)(g_rank_t + (size_t)n * (WINDOW * EE));
        ((float4*)rank_row)[tid] = rsrc[tid];
    }
    __syncthreads();

    // stats: one (tw, ee) task per thread, single pass
    {
        int tw = tid >> 3, ee = tid & 7;
        int te = 19 + tw;

        float s20 = 0.f, q20 = 0.f, mx20 = -1e30f, mn20 = 1e30f;
        float s5 = 0.f, q5 = 0.f, mx5 = -1e30f, mn5 = 1e30f;
#pragma unroll
        for (int j = 0; j < 20; j++) {
            float v = xe[te - 19 + j][ee];
            s20 += v; q20 = fmaf(v, v, q20);
            mx20 = fmaxf(mx20, v); mn20 = fminf(mn20, v);
            if (j >= 15) {
                s5 += v; q5 = fmaf(v, v, q5);
                mx5 = fmaxf(mx5, v); mn5 = fminf(mn5, v);
            }
        }
        float m20 = s20 * 0.05f;
        float m5  = s5 * 0.2f;
        float sd20 = sqrtf(fmaxf(fmaf(-s20, m20, q20), 0.f) * (1.0f / 19.0f));
        float sd5  = sqrtf(fmaxf(fmaf(-s5, m5, q5), 0.f) * 0.25f);

        float* st = stats + tw * 8 + ee;
        st[0 * SID_STRIDE] = m5;   st[1 * SID_STRIDE] = sd5;
        st[2 * SID_STRIDE] = mx5;  st[3 * SID_STRIDE] = mn5;
        st[4 * SID_STRIDE] = m20;  st[5 * SID_STRIDE] = sd20;
        st[6 * SID_STRIDE] = mx20; st[7 * SID_STRIDE] = mn20;
    }
    __syncthreads();

    // conv: two threads per channel, each covering 18 of 36 outputs
    float acc[18];
#pragma unroll
    for (int j = 0; j < 18; j++) acc[j] = 0.f;

    const int hh = (tid >= 160) ? 1 : 0;
    const int c  = tid - hh * 160;
    const int l0 = hh * 18;

    if (c < INCH) {
        const float* wp = conv_w + 127 * (INCH * 5) + c * 5;
        float w0 = __ldg(wp + 0), w1 = __ldg(wp + 1), w2 = __ldg(wp + 2),
              w3 = __ldg(wp + 3), w4 = __ldg(wp + 4);

        if (c < FDIM) {
            const float* src = xn + (24 + l0) * FDIM + c;
#pragma unroll
            for (int tt = 0; tt < 22; tt++) {
                float v = __ldg(src + tt * FDIM);
#pragma unroll
                for (int k = 0; k < 5; k++) {
                    int j = tt - k;
                    if (j >= 0 && j < 18) {
                        float wk = (k == 0) ? w0 : (k == 1) ? w1 : (k == 2) ? w2 : (k == 3) ? w3 : w4;
                        acc[j] += v * wk;
                    }
                }
            }
        } else {
            int cc = c - FDIM;
            int grp = (cc >= 40) ? 1 : 0;
            int r = cc - grp * 40;
            int se = r >> 3;
            int ee = r & 7;
            const float* s_src;
            if (se == 2) {
                s_src = rank_row + ee;
            } else {
                int statid = (se < 2 ? se : se - 1) + grp * 4;
                s_src = stats + statid * SID_STRIDE + ee;
            }
            s_src += l0 * 8;
#pragma unroll
            for (int tt = 0; tt < 22; tt++) {
                float v = s_src[tt * 8];
#pragma unroll
                for (int k = 0; k < 5; k++) {
                    int j = tt - k;
                    if (j >= 0 && j < 18) {
                        float wk = (k == 0) ? w0 : (k == 1) ? w1 : (k == 2) ? w2 : (k == 3) ? w3 : w4;
                        acc[j] += v * wk;
                    }
                }
            }
        }
    }

    // 2-level butterfly: lane holds sum of its group-of-4 {l, l^8, l^16, l^24}
#pragma unroll
    for (int j = 0; j < 18; j++) {
        float a = acc[j];
        a += __shfl_xor_sync(0xFFFFFFFFu, a, 16);
        a += __shfl_xor_sync(0xFFFFFFFFu, a, 8);
        acc[j] = a;
    }
    {
        const int w = tid >> 5;
        if ((tid & 31) < 8) {
#pragma unroll
            for (int j = 0; j < 18; j++) red[w * 8 + (tid & 7)][j] = acc[j];
        }
    }
    __syncthreads();

    if (tid < LOUT) {
        int h2 = (tid >= 18) ? 1 : 0;
        int j = tid - h2 * 18;
        const float* rp = &red[h2 * 40][j];
        float s = __ldg(conv_b + 127);
#pragma unroll
        for (int i = 0; i < 40; i++) s += rp[i * 18];
        float hv = (s >= 0.f) ? s : 0.01f * s;
        fin[tid] = hv * __ldg(lin_w + tid);
    }
    __syncthreads();

    if (tid == 0) {
        float s = __ldg(lin_b);
        for (int l = 0; l < LOUT; l++) s += fin[l];
        out[n] = s;
    }
}

// ---------------------------------------------------------------------------
extern "C" void kernel_launch(void* const* d_in, const int* in_sizes, int n_in,
                              void* d_out, int out_size) {
    const float* x      = (const float*)d_in[0];
    const float* conv_w = (const float*)d_in[1];
    const float* conv_b = (const float*)d_in[2];
    const float* lin_w  = (const float*)d_in[3];
    const float* lin_b  = (const float*)d_in[4];
    float* out = (float*)d_out;

    cudaFuncSetAttribute(rank_kernel, cudaFuncAttributeMaxDynamicSharedMemorySize, SMEM_R);

    rank_kernel<<<WINDOW * EE, RT, SMEM_R>>>(x);
    transpose_kernel<<<dim3((WINDOW * EE) / 32, NSTOCK / 32), dim3(32, 32)>>>();
    main_kernel<<<NSTOCK, 320>>>(x, conv_w, conv_b, lin_w, lin_b, out);
}

// round 11
// speedup vs baseline: 2.2352x; 1.0480x over previous
#include <cuda_runtime.h>
#include <cstdint>

#define WINDOW 40
#define EE 8
#define NSTOCK 8000
#define TDIM 64
#define FDIM 64
#define INCH 144
#define LOUT 36

__device__ float g_rank[WINDOW * EE * NSTOCK];      // [col][n]
__device__ float g_rank_t[NSTOCK * WINDOW * EE];    // [n][col]

// ---------------------------------------------------------------------------
// Kernel A: exact descending rank. Monotone value-space binning
// l2 = clamp(floor((v+4)*1024), 0, 8191), u32 histogram (one atomic round,
// old value = within-bin index), one prefix, atomic-free scatter,
// exact u64 in-bin scan with singleton fast path.
// smem: hist 8196 w (32784 B) + pack 8000 u64 (64000 B) = 96784 B -> 2 CTAs/SM
// ---------------------------------------------------------------------------
#define RT 512
#define HISTW 8196
#define SMEM_R (HISTW * 4 + NSTOCK * 8)

__device__ __forceinline__ unsigned int okey(float f) {
    unsigned int u = __float_as_uint(f);
    return (u & 0x80000000u) ? ~u : (u | 0x80000000u);
}

__global__ void __launch_bounds__(RT, 2) rank_kernel(const float* __restrict__ x) {
    extern __shared__ unsigned char smem_raw[];
    unsigned int* hist = (unsigned int*)smem_raw;                      // 8192 bins u32 + sentinel
    unsigned long long* pack = (unsigned long long*)(smem_raw + HISTW * 4);

    __shared__ unsigned int wsum[16];

    const int col = blockIdx.x;
    const int tw  = col >> 3;
    const int e   = col & 7;
    const int tid = threadIdx.x;
    const unsigned int lane = tid & 31u;
    const unsigned int wid  = tid >> 5;

    // zero histogram (8192 words via uint4)
    {
        uint4 z4 = make_uint4(0u, 0u, 0u, 0u);
        uint4* hv = (uint4*)hist;
#pragma unroll
        for (int i = 0; i < 4; i++) hv[tid + (i << 9)] = z4;
        if (tid == 0) { hist[8192] = 0u; hist[8193] = 0u; hist[8194] = 0u; hist[8195] = 0u; }
    }
    __syncthreads();

    const float* basep = x + (24 + tw) * FDIM + e;

    // P1: load value, bin, histogram atomic (old = within-bin index)
    unsigned int rk[16], lv[16];
#pragma unroll
    for (int i = 0; i < 16; i++) {
        int n = tid + (i << 9);
        if (n < NSTOCK) {
            float v = __ldg(basep + (size_t)n * (TDIM * FDIM));
            rk[i] = okey(v);
            int b = __float2int_rd(fmaf(v, 1024.0f, 4096.0f));
            b = (b < 0) ? 0 : (b > 8191 ? 8191 : b);
            unsigned int idx = atomicAdd(&hist[b], 1u);
            lv[i] = ((unsigned int)b << 16) | idx;
        }
    }
    __syncthreads();

    // exclusive prefix over 8192 u32 bins (16 bins/thread via uint4)
    {
        uint4* hv = (uint4*)hist;
        uint4 a[4];
        unsigned int s = 0;
#pragma unroll
        for (int j = 0; j < 4; j++) {
            a[j] = hv[tid * 4 + j];
            s += a[j].x + a[j].y + a[j].z + a[j].w;
        }
        unsigned int v = s;
#pragma unroll
        for (int o = 1; o < 32; o <<= 1) {
            unsigned int t = __shfl_up_sync(0xFFFFFFFFu, v, o);
            if (lane >= (unsigned)o) v += t;
        }
        if (lane == 31u) wsum[wid] = v;
        __syncthreads();
        if (wid == 0) {
            unsigned int orig = (lane < 16u) ? wsum[lane] : 0u;
            unsigned int w = orig;
#pragma unroll
            for (int o = 1; o < 32; o <<= 1) {
                unsigned int t = __shfl_up_sync(0xFFFFFFFFu, w, o);
                if (lane >= (unsigned)o) w += t;
            }
            if (lane < 16u) wsum[lane] = w - orig;
        }
        __syncthreads();
        unsigned int run = wsum[wid] + (v - s);
#pragma unroll
        for (int j = 0; j < 4; j++) {
            unsigned int* p = &a[j].x;
#pragma unroll
            for (int k = 0; k < 4; k++) {
                unsigned int c = p[k];
                p[k] = run;
                run += c;
            }
            hv[tid * 4 + j] = a[j];
        }
        if (tid == 0) hist[8192] = (unsigned int)NSTOCK;               // sentinel
    }
    __syncthreads();

    // P3: scatter u64 tie-break keys (no atomics): pos = start(b) + idx
#pragma unroll
    for (int i = 0; i < 16; i++) {
        int n = tid + (i << 9);
        if (n < NSTOCK) {
            unsigned int b = lv[i] >> 16;
            unsigned int idx = lv[i] & 0xFFFFu;
            pack[hist[b] + idx] = ((unsigned long long)rk[i] << 13) | (8191u - (unsigned)n);
        }
    }
    __syncthreads();

    // P4: rank = above-segment + in-segment strictly-greater; coalesced store
    float* dst = g_rank + (size_t)col * NSTOCK;
#pragma unroll
    for (int i = 0; i < 16; i++) {
        int n = tid + (i << 9);
        if (n < NSTOCK) {
            unsigned int b = lv[i] >> 16;
            unsigned int start = hist[b];
            unsigned int end = hist[b + 1];
            unsigned int g = (unsigned int)NSTOCK - end;
            if (end - start > 1u) {
                unsigned long long K = ((unsigned long long)rk[i] << 13) | (8191u - (unsigned)n);
                for (unsigned int q = start; q < end; q++)
                    g += (pack[q] > K) ? 1u : 0u;
            }
            dst[n] = (float)g * (1.0f / (float)NSTOCK);
        }
    }
}

// ---------------------------------------------------------------------------
// Transpose [col][n] -> [n][col]
// ---------------------------------------------------------------------------
__global__ void transpose_kernel() {
    __shared__ float tile[32][33];
    const int c0 = blockIdx.x * 32;
    const int n0 = blockIdx.y * 32;
    const int tx = threadIdx.x, ty = threadIdx.y;
    tile[ty][tx] = g_rank[(size_t)(c0 + ty) * NSTOCK + n0 + tx];
    __syncthreads();
    g_rank_t[(size_t)(n0 + ty) * (WINDOW * EE) + c0 + tx] = tile[tx][ty];
}

// ---------------------------------------------------------------------------
// Kernel B: fused stats + conv (out-channel 127) + linear.
// ---------------------------------------------------------------------------
#define SID_STRIDE 328

__global__ void __launch_bounds__(320) main_kernel(
    const float* __restrict__ x,
    const float* __restrict__ conv_w,
    const float* __restrict__ conv_b,
    const float* __restrict__ lin_w,
    const float* __restrict__ lin_b,
    float* __restrict__ out)
{
    __shared__ __align__(16) float xe[59][8];
    __shared__ __align__(16) float stats[8 * SID_STRIDE];
    __shared__ __align__(16) float rank_row[WINDOW * EE];
    __shared__ float red[80][18];
    __shared__ float fin[LOUT];

    const int n = blockIdx.x;
    const int tid = threadIdx.x;
    const float* xn = x + (size_t)n * (TDIM * FDIM);

    // load xe = x[n, 5:64, 0:8] with float4 (118 vector loads)
    if (tid < 118) {
        int row = tid >> 1, half = tid & 1;
        float4 v = *(const float4*)(xn + (5 + row) * FDIM + half * 4);
        *(float4*)(&xe[row][half * 4]) = v;
    }
    // load rank row (contiguous float4)
    if (tid >= 128 && tid < 128 + (WINDOW * EE) / 4) {
        const float4* rsrc = (const float4*)(g_rank_t + (size_t)n * (WINDOW * EE));
        ((float4*)rank_row)[tid - 128] = rsrc[tid - 128];
    }
    __syncthreads();

    // stats: one (tw, ee) task per thread, single pass
    {
        int tw = tid >> 3, ee = tid & 7;
        int te = 19 + tw;

        float s20 = 0.f, q20 = 0.f, mx20 = -1e30f, mn20 = 1e30f;
        float s5 = 0.f, q5 = 0.f, mx5 = -1e30f, mn5 = 1e30f;
#pragma unroll
        for (int j = 0; j < 20; j++) {
            float v = xe[te - 19 + j][ee];
            s20 += v; q20 = fmaf(v, v, q20);
            mx20 = fmaxf(mx20, v); mn20 = fminf(mn20, v);
            if (j >= 15) {
                s5 += v; q5 = fmaf(v, v, q5);
                mx5 = fmaxf(mx5, v); mn5 = fminf(mn5, v);
            }
        }
        float m20 = s20 * 0.05f;
        float m5  = s5 * 0.2f;
        float sd20 = sqrtf(fmaxf(fmaf(-s20, m20, q20), 0.f) * (1.0f / 19.0f));
        float sd5  = sqrtf(fmaxf(fmaf(-s5, m5, q5), 0.f) * 0.25f);

        float* st = stats + tw * 8 + ee;
        st[0 * SID_STRIDE] = m5;   st[1 * SID_STRIDE] = sd5;
        st[2 * SID_STRIDE] = mx5;  st[3 * SID_STRIDE] = mn5;
        st[4 * SID_STRIDE] = m20;  st[5 * SID_STRIDE] = sd20;
        st[6 * SID_STRIDE] = mx20; st[7 * SID_STRIDE] = mn20;
    }
    __syncthreads();

    // conv: two threads per channel, each covering 18 of 36 outputs
    float acc[18];
#pragma unroll
    for (int j = 0; j < 18; j++) acc[j] = 0.f;

    const int hh = (tid >= 160) ? 1 : 0;
    const int c  = tid - hh * 160;
    const int l0 = hh * 18;

    if (c < INCH) {
        const float* wp = conv_w + 127 * (INCH * 5) + c * 5;
        float w0 = __ldg(wp + 0), w1 = __ldg(wp + 1), w2 = __ldg(wp + 2),
              w3 = __ldg(wp + 3), w4 = __ldg(wp + 4);

        if (c < FDIM) {
            const float* src = xn + (24 + l0) * FDIM + c;
#pragma unroll
            for (int tt = 0; tt < 22; tt++) {
                float v = __ldg(src + tt * FDIM);
#pragma unroll
                for (int k = 0; k < 5; k++) {
                    int j = tt - k;
                    if (j >= 0 && j < 18) {
                        float wk = (k == 0) ? w0 : (k == 1) ? w1 : (k == 2) ? w2 : (k == 3) ? w3 : w4;
                        acc[j] += v * wk;
                    }
                }
            }
        } else {
            int cc = c - FDIM;
            int grp = (cc >= 40) ? 1 : 0;
            int r = cc - grp * 40;
            int se = r >> 3;
            int ee = r & 7;
            const float* s_src;
            if (se == 2) {
                s_src = rank_row + ee;
            } else {
                int statid = (se < 2 ? se : se - 1) + grp * 4;
                s_src = stats + statid * SID_STRIDE + ee;
            }
            s_src += l0 * 8;
#pragma unroll
            for (int tt = 0; tt < 22; tt++) {
                float v = s_src[tt * 8];
#pragma unroll
                for (int k = 0; k < 5; k++) {
                    int j = tt - k;
                    if (j >= 0 && j < 18) {
                        float wk = (k == 0) ? w0 : (k == 1) ? w1 : (k == 2) ? w2 : (k == 3) ? w3 : w4;
                        acc[j] += v * wk;
                    }
                }
            }
        }
    }

    // 2-level butterfly: lane holds sum of its group-of-4 {l, l^8, l^16, l^24}
#pragma unroll
    for (int j = 0; j < 18; j++) {
        float a = acc[j];
        a += __shfl_xor_sync(0xFFFFFFFFu, a, 16);
        a += __shfl_xor_sync(0xFFFFFFFFu, a, 8);
        acc[j] = a;
    }
    {
        const int w = tid >> 5;
        if ((tid & 31) < 8) {
#pragma unroll
            for (int j = 0; j < 18; j++) red[w * 8 + (tid & 7)][j] = acc[j];
        }
    }
    __syncthreads();

    if (tid < LOUT) {
        int h2 = (tid >= 18) ? 1 : 0;
        int j = tid - h2 * 18;
        const float* rp = &red[h2 * 40][j];
        float s = __ldg(conv_b + 127);
#pragma unroll
        for (int i = 0; i < 40; i++) s += rp[i * 18];
        float hv = (s >= 0.f) ? s : 0.01f * s;
        fin[tid] = hv * __ldg(lin_w + tid);
    }
    __syncthreads();

    if (tid == 0) {
        float s = __ldg(lin_b);
        for (int l = 0; l < LOUT; l++) s += fin[l];
        out[n] = s;
    }
}

// ---------------------------------------------------------------------------
extern "C" void kernel_launch(void* const* d_in, const int* in_sizes, int n_in,
                              void* d_out, int out_size) {
    const float* x      = (const float*)d_in[0];
    const float* conv_w = (const float*)d_in[1];
    const float* conv_b = (const float*)d_in[2];
    const float* lin_w  = (const float*)d_in[3];
    const float* lin_b  = (const float*)d_in[4];
    float* out = (float*)d_out;

    cudaFuncSetAttribute(rank_kernel, cudaFuncAttributeMaxDynamicSharedMemorySize, SMEM_R);

    rank_kernel<<<WINDOW * EE, RT, SMEM_R>>>(x);
    transpose_kernel<<<dim3((WINDOW * EE) / 32, NSTOCK / 32), dim3(32, 32)>>>();
    main_kernel<<<NSTOCK, 320>>>(x, conv_w, conv_b, lin_w, lin_b, out);
}

// round 12
// speedup vs baseline: 2.5304x; 1.1321x over previous
#include <cuda_runtime.h>
#include <cstdint>

#define WINDOW 40
#define EE 8
#define NSTOCK 8000
#define TDIM 64
#define FDIM 64
#define INCH 144
#define LOUT 36

__device__ float g_xcol[WINDOW * EE * NSTOCK];      // [col][n]  staged slice
__device__ float g_rank[WINDOW * EE * NSTOCK];      // [col][n]
__device__ float g_rank_t[NSTOCK * WINDOW * EE];    // [n][col]

// ---------------------------------------------------------------------------
// Gather: x[:, 24:64, 0:8] -> g_xcol[col][n], full sector efficiency.
// grid (40, 63), block 256: each block stages 128 n for one tw (8 cols).
// ---------------------------------------------------------------------------
__global__ void __launch_bounds__(256) gather_kernel(const float* __restrict__ x) {
    __shared__ float tile[8][128];
    const int twv = blockIdx.x;
    const int n0 = blockIdx.y * 128;
    const int t = threadIdx.x;

    {
        int nl = t >> 1, half = t & 1;
        int n = n0 + nl;
        if (n < NSTOCK) {
            float4 v = *(const float4*)(x + (size_t)n * (TDIM * FDIM) + (24 + twv) * FDIM + half * 4);
            tile[half * 4 + 0][nl] = v.x;
            tile[half * 4 + 1][nl] = v.y;
            tile[half * 4 + 2][nl] = v.z;
            tile[half * 4 + 3][nl] = v.w;
        }
    }
    __syncthreads();
    {
        int idx = t * 4;
        int c = idx >> 7, nl = idx & 127;
        if (n0 + nl + 3 < NSTOCK) {
            float4 v = *(const float4*)(&tile[c][nl]);
            *(float4*)(g_xcol + (size_t)(twv * 8 + c) * NSTOCK + n0 + nl) = v;
        } else {
            for (int j = 0; j < 4; j++)
                if (n0 + nl + j < NSTOCK)
                    g_xcol[(size_t)(twv * 8 + c) * NSTOCK + n0 + nl + j] = tile[c][nl + j];
        }
    }
}

// ---------------------------------------------------------------------------
// Kernel A: exact descending rank. Monotone value-space binning, u32 histogram
// (atomic old = within-bin index), one prefix, atomic-free scatter, exact u64
// in-bin scan with singleton fast path. Input now contiguous per column.
// smem: hist 8196 w + pack 8000 u64 = 96784 B -> 2 CTAs/SM
// ---------------------------------------------------------------------------
#define RT 512
#define HISTW 8196
#define SMEM_R (HISTW * 4 + NSTOCK * 8)

__device__ __forceinline__ unsigned int okey(float f) {
    unsigned int u = __float_as_uint(f);
    return (u & 0x80000000u) ? ~u : (u | 0x80000000u);
}

__global__ void __launch_bounds__(RT, 2) rank_kernel() {
    extern __shared__ unsigned char smem_raw[];
    unsigned int* hist = (unsigned int*)smem_raw;
    unsigned long long* pack = (unsigned long long*)(smem_raw + HISTW * 4);

    __shared__ unsigned int wsum[16];

    const int col = blockIdx.x;
    const int tid = threadIdx.x;
    const unsigned int lane = tid & 31u;
    const unsigned int wid  = tid >> 5;

    {
        uint4 z4 = make_uint4(0u, 0u, 0u, 0u);
        uint4* hv = (uint4*)hist;
#pragma unroll
        for (int i = 0; i < 4; i++) hv[tid + (i << 9)] = z4;
        if (tid == 0) { hist[8192] = 0u; hist[8193] = 0u; hist[8194] = 0u; hist[8195] = 0u; }
    }
    __syncthreads();

    const float* colp = g_xcol + (size_t)col * NSTOCK;

    // P1: coalesced contiguous loads, bin, histogram atomic (old = index)
    unsigned int rk[16], lv[16];
#pragma unroll
    for (int i = 0; i < 16; i++) {
        int n = tid + (i << 9);
        if (n < NSTOCK) {
            float v = __ldg(colp + n);
            rk[i] = okey(v);
            int b = __float2int_rd(fmaf(v, 1024.0f, 4096.0f));
            b = (b < 0) ? 0 : (b > 8191 ? 8191 : b);
            unsigned int idx = atomicAdd(&hist[b], 1u);
            lv[i] = ((unsigned int)b << 16) | idx;
        }
    }
    __syncthreads();

    // exclusive prefix over 8192 u32 bins (16/thread via uint4)
    {
        uint4* hv = (uint4*)hist;
        uint4 a[4];
        unsigned int s = 0;
#pragma unroll
        for (int j = 0; j < 4; j++) {
            a[j] = hv[tid * 4 + j];
            s += a[j].x + a[j].y + a[j].z + a[j].w;
        }
        unsigned int v = s;
#pragma unroll
        for (int o = 1; o < 32; o <<= 1) {
            unsigned int t = __shfl_up_sync(0xFFFFFFFFu, v, o);
            if (lane >= (unsigned)o) v += t;
        }
        if (lane == 31u) wsum[wid] = v;
        __syncthreads();
        if (wid == 0) {
            unsigned int orig = (lane < 16u) ? wsum[lane] : 0u;
            unsigned int w = orig;
#pragma unroll
            for (int o = 1; o < 32; o <<= 1) {
                unsigned int t = __shfl_up_sync(0xFFFFFFFFu, w, o);
                if (lane >= (unsigned)o) w += t;
            }
            if (lane < 16u) wsum[lane] = w - orig;
        }
        __syncthreads();
        unsigned int run = wsum[wid] + (v - s);
#pragma unroll
        for (int j = 0; j < 4; j++) {
            unsigned int* p = &a[j].x;
#pragma unroll
            for (int k = 0; k < 4; k++) {
                unsigned int c = p[k];
                p[k] = run;
                run += c;
            }
            hv[tid * 4 + j] = a[j];
        }
        if (tid == 0) hist[8192] = (unsigned int)NSTOCK;
    }
    __syncthreads();

    // P3: scatter u64 tie-break keys (no atomics)
#pragma unroll
    for (int i = 0; i < 16; i++) {
        int n = tid + (i << 9);
        if (n < NSTOCK) {
            unsigned int b = lv[i] >> 16;
            unsigned int idx = lv[i] & 0xFFFFu;
            pack[hist[b] + idx] = ((unsigned long long)rk[i] << 13) | (8191u - (unsigned)n);
        }
    }
    __syncthreads();

    // P4: rank = above-segment + in-segment strictly-greater; coalesced store
    float* dst = g_rank + (size_t)col * NSTOCK;
#pragma unroll
    for (int i = 0; i < 16; i++) {
        int n = tid + (i << 9);
        if (n < NSTOCK) {
            unsigned int b = lv[i] >> 16;
            unsigned int start = hist[b];
            unsigned int end = hist[b + 1];
            unsigned int g = (unsigned int)NSTOCK - end;
            if (end - start > 1u) {
                unsigned long long K = ((unsigned long long)rk[i] << 13) | (8191u - (unsigned)n);
                for (unsigned int q = start; q < end; q++)
                    g += (pack[q] > K) ? 1u : 0u;
            }
            dst[n] = (float)g * (1.0f / (float)NSTOCK);
        }
    }
}

// ---------------------------------------------------------------------------
// Transpose [col][n] -> [n][col]
// ---------------------------------------------------------------------------
__global__ void transpose_kernel() {
    __shared__ float tile[32][33];
    const int c0 = blockIdx.x * 32;
    const int n0 = blockIdx.y * 32;
    const int tx = threadIdx.x, ty = threadIdx.y;
    tile[ty][tx] = g_rank[(size_t)(c0 + ty) * NSTOCK + n0 + tx];
    __syncthreads();
    g_rank_t[(size_t)(n0 + ty) * (WINDOW * EE) + c0 + tx] = tile[tx][ty];
}

// ---------------------------------------------------------------------------
// Kernel B: fused stats + conv (out-channel 127) + linear.
// ---------------------------------------------------------------------------
#define SID_STRIDE 328

__global__ void __launch_bounds__(320) main_kernel(
    const float* __restrict__ x,
    const float* __restrict__ conv_w,
    const float* __restrict__ conv_b,
    const float* __restrict__ lin_w,
    const float* __restrict__ lin_b,
    float* __restrict__ out)
{
    __shared__ __align__(16) float xe[59][8];
    __shared__ __align__(16) float stats[8 * SID_STRIDE];
    __shared__ __align__(16) float rank_row[WINDOW * EE];
    __shared__ float red[80][18];
    __shared__ float fin[LOUT];

    const int n = blockIdx.x;
    const int tid = threadIdx.x;
    const float* xn = x + (size_t)n * (TDIM * FDIM);

    if (tid < 118) {
        int row = tid >> 1, half = tid & 1;
        float4 v = *(const float4*)(xn + (5 + row) * FDIM + half * 4);
        *(float4*)(&xe[row][half * 4]) = v;
    }
    if (tid >= 128 && tid < 128 + (WINDOW * EE) / 4) {
        const float4* rsrc = (const float4*)(g_rank_t + (size_t)n * (WINDOW * EE));
        ((float4*)rank_row)[tid - 128] = rsrc[tid - 128];
    }
    __syncthreads();

    // stats: one (tw, ee) task per thread, single pass
    {
        int tw = tid >> 3, ee = tid & 7;
        int te = 19 + tw;

        float s20 = 0.f, q20 = 0.f, mx20 = -1e30f, mn20 = 1e30f;
        float s5 = 0.f, q5 = 0.f, mx5 = -1e30f, mn5 = 1e30f;
#pragma unroll
        for (int j = 0; j < 20; j++) {
            float v = xe[te - 19 + j][ee];
            s20 += v; q20 = fmaf(v, v, q20);
            mx20 = fmaxf(mx20, v); mn20 = fminf(mn20, v);
            if (j >= 15) {
                s5 += v; q5 = fmaf(v, v, q5);
                mx5 = fmaxf(mx5, v); mn5 = fminf(mn5, v);
            }
        }
        float m20 = s20 * 0.05f;
        float m5  = s5 * 0.2f;
        float sd20 = sqrtf(fmaxf(fmaf(-s20, m20, q20), 0.f) * (1.0f / 19.0f));
        float sd5  = sqrtf(fmaxf(fmaf(-s5, m5, q5), 0.f) * 0.25f);

        float* st = stats + tw * 8 + ee;
        st[0 * SID_STRIDE] = m5;   st[1 * SID_STRIDE] = sd5;
        st[2 * SID_STRIDE] = mx5;  st[3 * SID_STRIDE] = mn5;
        st[4 * SID_STRIDE] = m20;  st[5 * SID_STRIDE] = sd20;
        st[6 * SID_STRIDE] = mx20; st[7 * SID_STRIDE] = mn20;
    }
    __syncthreads();

    // conv: two threads per channel, each covering 18 of 36 outputs
    float acc[18];
#pragma unroll
    for (int j = 0; j < 18; j++) acc[j] = 0.f;

    const int hh = (tid >= 160) ? 1 : 0;
    const int c  = tid - hh * 160;
    const int l0 = hh * 18;

    if (c < INCH) {
        const float* wp = conv_w + 127 * (INCH * 5) + c * 5;
        float w0 = __ldg(wp + 0), w1 = __ldg(wp + 1), w2 = __ldg(wp + 2),
              w3 = __ldg(wp + 3), w4 = __ldg(wp + 4);

        if (c < FDIM) {
            const float* src = xn + (24 + l0) * FDIM + c;
#pragma unroll
            for (int tt = 0; tt < 22; tt++) {
                float v = __ldg(src + tt * FDIM);
#pragma unroll
                for (int k = 0; k < 5; k++) {
                    int j = tt - k;
                    if (j >= 0 && j < 18) {
                        float wk = (k == 0) ? w0 : (k == 1) ? w1 : (k == 2) ? w2 : (k == 3) ? w3 : w4;
                        acc[j] += v * wk;
                    }
                }
            }
        } else {
            int cc = c - FDIM;
            int grp = (cc >= 40) ? 1 : 0;
            int r = cc - grp * 40;
            int se = r >> 3;
            int ee = r & 7;
            const float* s_src;
            if (se == 2) {
                s_src = rank_row + ee;
            } else {
                int statid = (se < 2 ? se : se - 1) + grp * 4;
                s_src = stats + statid * SID_STRIDE + ee;
            }
            s_src += l0 * 8;
#pragma unroll
            for (int tt = 0; tt < 22; tt++) {
                float v = s_src[tt * 8];
#pragma unroll
                for (int k = 0; k < 5; k++) {
                    int j = tt - k;
                    if (j >= 0 && j < 18) {
                        float wk = (k == 0) ? w0 : (k == 1) ? w1 : (k == 2) ? w2 : (k == 3) ? w3 : w4;
                        acc[j] += v * wk;
                    }
                }
            }
        }
    }

    // 2-level butterfly -> 8 partials/warp -> smem -> 36-thread finish
#pragma unroll
    for (int j = 0; j < 18; j++) {
        float a = acc[j];
        a += __shfl_xor_sync(0xFFFFFFFFu, a, 16);
        a += __shfl_xor_sync(0xFFFFFFFFu, a, 8);
        acc[j] = a;
    }
    {
        const int w = tid >> 5;
        if ((tid & 31) < 8) {
#pragma unroll
            for (int j = 0; j < 18; j++) red[w * 8 + (tid & 7)][j] = acc[j];
        }
    }
    __syncthreads();

    if (tid < LOUT) {
        int h2 = (tid >= 18) ? 1 : 0;
        int j = tid - h2 * 18;
        const float* rp = &red[h2 * 40][j];
        float s = __ldg(conv_b + 127);
#pragma unroll
        for (int i = 0; i < 40; i++) s += rp[i * 18];
        float hv = (s >= 0.f) ? s : 0.01f * s;
        fin[tid] = hv * __ldg(lin_w + tid);
    }
    __syncthreads();

    if (tid == 0) {
        float s = __ldg(lin_b);
        for (int l = 0; l < LOUT; l++) s += fin[l];
        out[n] = s;
    }
}

// ---------------------------------------------------------------------------
extern "C" void kernel_launch(void* const* d_in, const int* in_sizes, int n_in,
                              void* d_out, int out_size) {
    const float* x      = (const float*)d_in[0];
    const float* conv_w = (const float*)d_in[1];
    const float* conv_b = (const float*)d_in[2];
    const float* lin_w  = (const float*)d_in[3];
    const float* lin_b  = (const float*)d_in[4];
    float* out = (float*)d_out;

    cudaFuncSetAttribute(rank_kernel, cudaFuncAttributeMaxDynamicSharedMemorySize, SMEM_R);

    gather_kernel<<<dim3(WINDOW, (NSTOCK + 127) / 128), 256>>>(x);
    rank_kernel<<<WINDOW * EE, RT, SMEM_R>>>();
    transpose_kernel<<<dim3((WINDOW * EE) / 32, NSTOCK / 32), dim3(32, 32)>>>();
    main_kernel<<<NSTOCK, 320>>>(x, conv_w, conv_b, lin_w, lin_b, out);
}